// round 3
// baseline (speedup 1.0000x reference)
#include <cuda_runtime.h>

#define N_NODES 5000
#define BATCH   16
#define FEAT    512
#define NEDGE   160000
#define NCOL    64
#define FCOL    128
#define NTOT    (N_NODES*BATCH)   // 80000

// Scratch (device globals; no allocation allowed)
__device__ __align__(16) float g_h1  [N_NODES*BATCH*16];
__device__ __align__(16) float g_buf1[N_NODES*BATCH*16];
__device__ __align__(16) float g_h2  [N_NODES*BATCH*16];
__device__ __align__(16) float g_buf2[N_NODES*BATCH*16];
__device__ int   g_deg [N_NODES];
__device__ int   g_cursor[N_NODES];
__device__ int   g_rowstart[N_NODES+1];
__device__ float g_dinv[N_NODES];
__device__ __align__(8) int2 g_csr[NEDGE];   // x = src node, y = norm (float bits)
__device__ float g_col [BATCH*NCOL];
__device__ int   g_is64;

// ---- edge_index dtype detection: harness may store int64 as int32 words ----
// If int64 (little-endian, values < 5000): every odd int32 word is 0.
__global__ void k_detect(const int* __restrict__ ei){
    if (threadIdx.x == 0){
        int all0 = 1;
        for (int k = 0; k < 64; k++){
            if (ei[2*k + 1] != 0){ all0 = 0; break; }
        }
        g_is64 = all0;
    }
}
// idx in [0, 2*NEDGE): logical flat index into the [2, E] edge_index
__device__ __forceinline__ int edge_at(const int* __restrict__ ei, int idx){
    return g_is64 ? ei[2*idx] : ei[idx];
}

// ---- degree / CSR build (graph shared across batch) ----
__global__ void k_zero(){
    int n = blockIdx.x*blockDim.x + threadIdx.x;
    if (n < N_NODES){ g_deg[n] = 0; g_cursor[n] = 0; }
}
__global__ void k_count(const int* __restrict__ ei){
    int e = blockIdx.x*blockDim.x + threadIdx.x;
    if (e < NEDGE){
        int d = edge_at(ei, NEDGE + e);
        if (d >= 0 && d < N_NODES) atomicAdd(&g_deg[d], 1);
    }
}
__global__ void k_dinv(){
    int n = blockIdx.x*blockDim.x + threadIdx.x;
    if (n < N_NODES) g_dinv[n] = rsqrtf((float)(g_deg[n] + 1));
}
// single-block exclusive scan over 5000 degree counts
__global__ void __launch_bounds__(1024) k_scan(){
    __shared__ int part[1024];
    int t = threadIdx.x;
    const int CH = (N_NODES + 1023) / 1024;   // 5
    int base = t * CH;
    int s = 0;
    #pragma unroll
    for (int j = 0; j < CH; j++){ int idx = base + j; if (idx < N_NODES) s += g_deg[idx]; }
    part[t] = s; __syncthreads();
    for (int off = 1; off < 1024; off <<= 1){
        int v = (t >= off) ? part[t - off] : 0;
        __syncthreads();
        part[t] += v;
        __syncthreads();
    }
    int excl = (t == 0) ? 0 : part[t - 1];
    #pragma unroll
    for (int j = 0; j < CH; j++){
        int idx = base + j;
        if (idx < N_NODES){ g_rowstart[idx] = excl; excl += g_deg[idx]; }
    }
    if (t == 0) g_rowstart[N_NODES] = NEDGE;
}
__global__ void k_fill(const int* __restrict__ ei){
    int e = blockIdx.x*blockDim.x + threadIdx.x;
    if (e >= NEDGE) return;
    int s = edge_at(ei, e);
    int d = edge_at(ei, NEDGE + e);
    if (s < 0 || s >= N_NODES || d < 0 || d >= N_NODES) return;
    int pos = atomicAdd(&g_cursor[d], 1);
    float nrm = g_dinv[s] * g_dinv[d];
    g_csr[g_rowstart[d] + pos] = make_int2(s, __float_as_int(nrm));
}

// ---- GEMM1: h1[n][b][0:16] = X[b][n][:] @ W1 ----
__global__ void __launch_bounds__(256) k_gemm1(const float* __restrict__ X, const float* __restrict__ W1){
    __shared__ __align__(16) float ws[FEAT*16];
    for (int i = threadIdx.x; i < FEAT*16/4; i += 256)
        ((float4*)ws)[i] = ((const float4*)W1)[i];
    __syncthreads();
    int r = blockIdx.x*256 + threadIdx.x;
    if (r >= NTOT) return;
    int b = r / N_NODES, n = r - b*N_NODES;
    const float4* xr = (const float4*)X + (size_t)r*(FEAT/4);
    float acc[16];
    #pragma unroll
    for (int j = 0; j < 16; j++) acc[j] = 0.0f;
    #pragma unroll 2
    for (int k4 = 0; k4 < FEAT/4; k4++){
        float4 xv = xr[k4];
        const float* w0 = &ws[(k4*4 + 0)*16];
        const float* w1 = &ws[(k4*4 + 1)*16];
        const float* w2 = &ws[(k4*4 + 2)*16];
        const float* w3 = &ws[(k4*4 + 3)*16];
        #pragma unroll
        for (int j = 0; j < 16; j++){
            float a = acc[j];
            a = fmaf(xv.x, w0[j], a);
            a = fmaf(xv.y, w1[j], a);
            a = fmaf(xv.z, w2[j], a);
            a = fmaf(xv.w, w3[j], a);
            acc[j] = a;
        }
    }
    float4* dst = (float4*)g_h1 + ((size_t)n*16 + b)*4;
    #pragma unroll
    for (int q = 0; q < 4; q++)
        dst[q] = make_float4(acc[4*q+0], acc[4*q+1], acc[4*q+2], acc[4*q+3]);
}

// ---- gather: buf[n][*] = dinv[n]^2 * h[n][*] + sum_{e: dst=n} norm_e * h[src_e][*] ----
// 64 threads per node (one float4 lane each), 4-deep unrolled edge loop (MLP=4).
__global__ void __launch_bounds__(256) k_gather(int layer){
    int gt = blockIdx.x*256 + threadIdx.x;
    int n = gt >> 6;
    int i = gt & 63;
    if (n >= N_NODES) return;
    const float4* h  = (const float4*)(layer ? g_h2  : g_h1);
    float4*       bf = (float4*)      (layer ? g_buf2 : g_buf1);
    float di = g_dinv[n];
    float sl = di * di;
    float4 v = h[n*64 + i];
    float4 acc = make_float4(v.x*sl, v.y*sl, v.z*sl, v.w*sl);
    int k   = g_rowstart[n];
    int end = g_rowstart[n+1];
    for (; k + 4 <= end; k += 4){
        int2 e0 = g_csr[k+0], e1 = g_csr[k+1], e2 = g_csr[k+2], e3 = g_csr[k+3];
        float4 u0 = h[e0.x*64 + i];
        float4 u1 = h[e1.x*64 + i];
        float4 u2 = h[e2.x*64 + i];
        float4 u3 = h[e3.x*64 + i];
        float n0 = __int_as_float(e0.y), n1 = __int_as_float(e1.y);
        float n2 = __int_as_float(e2.y), n3 = __int_as_float(e3.y);
        acc.x = fmaf(n0, u0.x, acc.x); acc.y = fmaf(n0, u0.y, acc.y);
        acc.z = fmaf(n0, u0.z, acc.z); acc.w = fmaf(n0, u0.w, acc.w);
        acc.x = fmaf(n1, u1.x, acc.x); acc.y = fmaf(n1, u1.y, acc.y);
        acc.z = fmaf(n1, u1.z, acc.z); acc.w = fmaf(n1, u1.w, acc.w);
        acc.x = fmaf(n2, u2.x, acc.x); acc.y = fmaf(n2, u2.y, acc.y);
        acc.z = fmaf(n2, u2.z, acc.z); acc.w = fmaf(n2, u2.w, acc.w);
        acc.x = fmaf(n3, u3.x, acc.x); acc.y = fmaf(n3, u3.y, acc.y);
        acc.z = fmaf(n3, u3.z, acc.z); acc.w = fmaf(n3, u3.w, acc.w);
    }
    for (; k < end; k++){
        int2 e = g_csr[k];
        float nr = __int_as_float(e.y);
        float4 u = h[e.x*64 + i];
        acc.x = fmaf(nr, u.x, acc.x); acc.y = fmaf(nr, u.y, acc.y);
        acc.z = fmaf(nr, u.z, acc.z); acc.w = fmaf(nr, u.w, acc.w);
    }
    bf[n*64 + i] = acc;
}

// ---- layer2 input transform: h2 = relu(buf1 + b1) @ W2 ----
__global__ void __launch_bounds__(256) k_xform2(const float* __restrict__ W2, const float* __restrict__ b1){
    __shared__ float sw[256];
    __shared__ float sb[16];
    sw[threadIdx.x] = W2[threadIdx.x];
    if (threadIdx.x < 16) sb[threadIdx.x] = b1[threadIdx.x];
    __syncthreads();
    int r = blockIdx.x*256 + threadIdx.x;
    if (r >= NTOT) return;
    const float4* in = (const float4*)g_buf1 + (size_t)r*4;
    float v[16];
    #pragma unroll
    for (int q=0;q<4;q++){
        float4 t = in[q];
        v[4*q+0]=t.x; v[4*q+1]=t.y; v[4*q+2]=t.z; v[4*q+3]=t.w;
    }
    #pragma unroll
    for (int j=0;j<16;j++) v[j] = fmaxf(v[j] + sb[j], 0.0f);
    float o[16];
    #pragma unroll
    for (int j=0;j<16;j++) o[j] = 0.0f;
    #pragma unroll
    for (int j=0;j<16;j++){
        float vj = v[j];
        #pragma unroll
        for (int jo=0;jo<16;jo++) o[jo] = fmaf(vj, sw[j*16+jo], o[jo]);
    }
    float4* out = (float4*)g_h2 + (size_t)r*4;
    #pragma unroll
    for (int q=0;q<4;q++)
        out[q] = make_float4(o[4*q+0], o[4*q+1], o[4*q+2], o[4*q+3]);
}

// ---- column MLP: col_logits[b*64+c] ----
__global__ void __launch_bounds__(256) k_colmlp(const float* __restrict__ CF, const float* __restrict__ cw1,
                                                const float* __restrict__ cb1, const float* __restrict__ cw2,
                                                const float* __restrict__ cb2){
    __shared__ __align__(16) float sw[FCOL*16];
    __shared__ float sb1[16], sw2[16];
    for (int i = threadIdx.x; i < FCOL*16/4; i += 256)
        ((float4*)sw)[i] = ((const float4*)cw1)[i];
    if (threadIdx.x < 16){ sb1[threadIdx.x]=cb1[threadIdx.x]; sw2[threadIdx.x]=cw2[threadIdx.x]; }
    __syncthreads();
    int r = blockIdx.x*256 + threadIdx.x;
    if (r >= BATCH*NCOL) return;
    const float4* xr = (const float4*)CF + (size_t)r*(FCOL/4);
    float acc[16];
    #pragma unroll
    for (int j=0;j<16;j++) acc[j] = sb1[j];
    for (int k4 = 0; k4 < FCOL/4; k4++){
        float4 xv = xr[k4];
        #pragma unroll
        for (int kk=0; kk<4; kk++){
            float xs = (kk==0)?xv.x:(kk==1)?xv.y:(kk==2)?xv.z:xv.w;
            #pragma unroll
            for (int j=0;j<16;j++) acc[j] = fmaf(xs, sw[(k4*4+kk)*16 + j], acc[j]);
        }
    }
    float sres = cb2[0];
    #pragma unroll
    for (int j=0;j<16;j++) sres = fmaf(fmaxf(acc[j], 0.0f), sw2[j], sres);
    g_col[r] = sres;
}

// ---- final: node head + broadcast add with col logits ----
__global__ void __launch_bounds__(256) k_final(const float* __restrict__ b2, const float* __restrict__ fcw,
                                               const float* __restrict__ fcb, float* __restrict__ out){
    __shared__ __align__(16) float scol[BATCH*NCOL];
    __shared__ float sb2[16], sfw[16];
    for (int i = threadIdx.x; i < BATCH*NCOL; i += 256) scol[i] = g_col[i];
    if (threadIdx.x < 16){ sb2[threadIdx.x]=b2[threadIdx.x]; sfw[threadIdx.x]=fcw[threadIdx.x]; }
    __syncthreads();
    int r = blockIdx.x*256 + threadIdx.x;
    if (r >= NTOT) return;
    int b = r / N_NODES, n = r - b*N_NODES;
    const float4* in = (const float4*)g_buf2 + ((size_t)n*16 + b)*4;
    float logit = fcb[0];
    #pragma unroll
    for (int q=0;q<4;q++){
        float4 t = in[q];
        logit = fmaf(fmaxf(t.x + sb2[4*q+0], 0.0f), sfw[4*q+0], logit);
        logit = fmaf(fmaxf(t.y + sb2[4*q+1], 0.0f), sfw[4*q+1], logit);
        logit = fmaf(fmaxf(t.z + sb2[4*q+2], 0.0f), sfw[4*q+2], logit);
        logit = fmaf(fmaxf(t.w + sb2[4*q+3], 0.0f), sfw[4*q+3], logit);
    }
    float4* o = (float4*)out + (size_t)r*16;          // out[b][n*64 + c]
    const float4* sc = (const float4*)scol + b*16;
    #pragma unroll
    for (int c4 = 0; c4 < 16; c4++){
        float4 cv = sc[c4];
        o[c4] = make_float4(logit+cv.x, logit+cv.y, logit+cv.z, logit+cv.w);
    }
}

extern "C" void kernel_launch(void* const* d_in, const int* in_sizes, int n_in,
                              void* d_out, int out_size){
    const float* X   = (const float*)d_in[0];
    const float* CF  = (const float*)d_in[1];
    const int*   ei  = (const int*)d_in[2];
    const float* W1  = (const float*)d_in[3];
    const float* b1  = (const float*)d_in[4];
    const float* W2  = (const float*)d_in[5];
    const float* b2  = (const float*)d_in[6];
    const float* fcw = (const float*)d_in[7];
    const float* fcb = (const float*)d_in[8];
    const float* cw1 = (const float*)d_in[9];
    const float* cb1 = (const float*)d_in[10];
    const float* cw2 = (const float*)d_in[11];
    const float* cb2 = (const float*)d_in[12];
    float* out = (float*)d_out;

    k_detect<<<1, 32>>>(ei);
    k_zero  <<<(N_NODES+255)/256, 256>>>();
    k_count <<<(NEDGE+255)/256, 256>>>(ei);
    k_dinv  <<<(N_NODES+255)/256, 256>>>();
    k_scan  <<<1, 1024>>>();
    k_fill  <<<(NEDGE+255)/256, 256>>>(ei);

    k_gemm1 <<<(NTOT+255)/256, 256>>>(X, W1);
    k_gather<<<(N_NODES*64+255)/256, 256>>>(0);

    k_xform2<<<(NTOT+255)/256, 256>>>(W2, b1);
    k_gather<<<(N_NODES*64+255)/256, 256>>>(1);

    k_colmlp<<<4, 256>>>(CF, cw1, cb1, cw2, cb2);
    k_final <<<(NTOT+255)/256, 256>>>(b2, fcw, fcb, out);
}

// round 4
// speedup vs baseline: 1.0676x; 1.0676x over previous
#include <cuda_runtime.h>

#define N_NODES 5000
#define BATCH   16
#define FEAT    512
#define NEDGE   160000
#define NCOL    64
#define FCOL    128
#define NTOT    (N_NODES*BATCH)   // 80000

// Scratch (device globals; no allocation allowed)
__device__ __align__(16) float g_h1  [N_NODES*BATCH*16];
__device__ __align__(16) float g_buf1[N_NODES*BATCH*16];
__device__ __align__(16) float g_h2  [N_NODES*BATCH*16];
__device__ __align__(16) float g_buf2[N_NODES*BATCH*16];
__device__ int   g_deg [N_NODES];
__device__ int   g_cursor[N_NODES];
__device__ int   g_rowstart[N_NODES+1];
__device__ float g_dinv[N_NODES];
__device__ __align__(16) int2 g_csr[NEDGE];   // x = src node, y = norm (float bits)
__device__ float g_col [BATCH*NCOL];
__device__ int   g_is64 = 1;   // converges to the same value every run (deterministic)

// ---- packed f32x2 helpers (Blackwell) ----
__device__ __forceinline__ unsigned long long splat2(float x){
    unsigned long long r; asm("mov.b64 %0, {%1, %1};" : "=l"(r) : "f"(x)); return r;
}
__device__ __forceinline__ unsigned long long ffma2(unsigned long long a, unsigned long long b, unsigned long long c){
    unsigned long long d; asm("fma.rn.f32x2 %0, %1, %2, %3;" : "=l"(d) : "l"(a), "l"(b), "l"(c)); return d;
}
__device__ __forceinline__ float2 unpack2(unsigned long long v){
    float2 r; asm("mov.b64 {%0, %1}, %2;" : "=f"(r.x), "=f"(r.y) : "l"(v)); return r;
}

__device__ __forceinline__ int edge_at(const int* __restrict__ ei, int idx){
    return g_is64 ? ei[2*idx] : ei[idx];
}

// ---- prep: zero counters + parallel int64-detection ----
__global__ void k_prep(const int* __restrict__ ei){
    int n = blockIdx.x*blockDim.x + threadIdx.x;
    if (n < N_NODES){ g_deg[n] = 0; g_cursor[n] = 0; }
    if (blockIdx.x == 0 && threadIdx.x < 64){
        // if data is int32, some odd word among first 128 is almost surely nonzero
        if (ei[2*threadIdx.x + 1] != 0) atomicExch(&g_is64, 0);
    }
}
__global__ void k_count(const int* __restrict__ ei){
    int e = blockIdx.x*blockDim.x + threadIdx.x;
    if (e < NEDGE){
        int d = edge_at(ei, NEDGE + e);
        if (d >= 0 && d < N_NODES) atomicAdd(&g_deg[d], 1);
    }
}
// single-block exclusive scan over 5000 degree counts (+ dinv)
__global__ void __launch_bounds__(1024) k_scan(){
    __shared__ int part[1024];
    int t = threadIdx.x;
    const int CH = (N_NODES + 1023) / 1024;   // 5
    int base = t * CH;
    int s = 0;
    #pragma unroll
    for (int j = 0; j < CH; j++){ int idx = base + j; if (idx < N_NODES) s += g_deg[idx]; }
    part[t] = s; __syncthreads();
    for (int off = 1; off < 1024; off <<= 1){
        int v = (t >= off) ? part[t - off] : 0;
        __syncthreads();
        part[t] += v;
        __syncthreads();
    }
    int excl = (t == 0) ? 0 : part[t - 1];
    #pragma unroll
    for (int j = 0; j < CH; j++){
        int idx = base + j;
        if (idx < N_NODES){
            int d = g_deg[idx];
            g_rowstart[idx] = excl; excl += d;
            g_dinv[idx] = rsqrtf((float)(d + 1));
        }
    }
    if (t == 0) g_rowstart[N_NODES] = NEDGE;
}
__global__ void k_fill(const int* __restrict__ ei){
    int e = blockIdx.x*blockDim.x + threadIdx.x;
    if (e >= NEDGE) return;
    int s = edge_at(ei, e);
    int d = edge_at(ei, NEDGE + e);
    if (s < 0 || s >= N_NODES || d < 0 || d >= N_NODES) return;
    int pos = atomicAdd(&g_cursor[d], 1);
    float nrm = g_dinv[s] * g_dinv[d];
    g_csr[g_rowstart[d] + pos] = make_int2(s, __float_as_int(nrm));
}

// ---- GEMM1: h1[n][b][0:16] = X[b][n][:] @ W1 ----
// 128 threads = 128 rows per block; X staged through padded smem tile (coalesced),
// W broadcast from smem, packed f32x2 FMA.
#define GR 128
#define KC 16
#define TSTRIDE 20   // padded floats per tile row: conflict-free LDS.128 (banks 20l%32 distinct per 8-lane phase)
__global__ void __launch_bounds__(GR) k_gemm1(const float* __restrict__ X, const float* __restrict__ W1){
    __shared__ __align__(16) float ws[FEAT*16];        // 32 KB, [k][j]
    __shared__ __align__(16) float tile[GR*TSTRIDE];   // 10 KB
    int t = threadIdx.x;
    for (int i = t; i < FEAT*16/4; i += GR)
        ((float4*)ws)[i] = ((const float4*)W1)[i];
    int row0 = blockIdx.x * GR;                         // 80000 = 625*128, exact
    const float4* Xb = (const float4*)X + (size_t)row0*(FEAT/4);
    unsigned long long acc[8] = {0,0,0,0,0,0,0,0};
    for (int c = 0; c < FEAT/KC; c++){                  // 32 chunks of 16 k
        __syncthreads();
        #pragma unroll
        for (int i = 0; i < 4; i++){                    // 512 float4 tile, 4 per thread
            int f  = t + GR*i;
            int rr = f >> 2, kq = f & 3;
            float4 v = Xb[(size_t)rr*(FEAT/4) + c*4 + kq];
            *((float4*)&tile[rr*TSTRIDE + kq*4]) = v;
        }
        __syncthreads();
        #pragma unroll
        for (int kq = 0; kq < 4; kq++){
            float4 xv = *((const float4*)&tile[t*TSTRIDE + kq*4]);
            int kbase = c*KC + kq*4;
            #pragma unroll
            for (int kk = 0; kk < 4; kk++){
                float xs = (kk==0)?xv.x:(kk==1)?xv.y:(kk==2)?xv.z:xv.w;
                unsigned long long x2 = splat2(xs);
                const ulonglong2* wk = (const ulonglong2*)&ws[(kbase+kk)*16];
                ulonglong2 w0 = wk[0], w1 = wk[1], w2 = wk[2], w3 = wk[3];
                acc[0]=ffma2(x2,w0.x,acc[0]); acc[1]=ffma2(x2,w0.y,acc[1]);
                acc[2]=ffma2(x2,w1.x,acc[2]); acc[3]=ffma2(x2,w1.y,acc[3]);
                acc[4]=ffma2(x2,w2.x,acc[4]); acc[5]=ffma2(x2,w2.y,acc[5]);
                acc[6]=ffma2(x2,w3.x,acc[6]); acc[7]=ffma2(x2,w3.y,acc[7]);
            }
        }
    }
    int r = row0 + t;
    int b = r / N_NODES, n = r - b*N_NODES;
    float4* dst = (float4*)g_h1 + ((size_t)n*16 + b)*4;
    #pragma unroll
    for (int q = 0; q < 4; q++){
        float2 lo = unpack2(acc[2*q]), hi = unpack2(acc[2*q+1]);
        dst[q] = make_float4(lo.x, lo.y, hi.x, hi.y);
    }
}

// ---- gather: buf[n][*] = dinv[n]^2 * h[n][*] + sum_{e: dst=n} norm_e * h[src_e][*] ----
// 64 threads per node (one float4 lane each), 8-deep unrolled edge loop.
__device__ __forceinline__ void fma4(float4& a, float nr, const float4& u){
    a.x = fmaf(nr, u.x, a.x); a.y = fmaf(nr, u.y, a.y);
    a.z = fmaf(nr, u.z, a.z); a.w = fmaf(nr, u.w, a.w);
}
__global__ void __launch_bounds__(256) k_gather(int layer){
    int gt = blockIdx.x*256 + threadIdx.x;
    int n = gt >> 6;
    int i = gt & 63;
    if (n >= N_NODES) return;
    const float4* __restrict__ h  = (const float4*)(layer ? g_h2  : g_h1);
    float4*       __restrict__ bf = (float4*)      (layer ? g_buf2 : g_buf1);
    float di = g_dinv[n];
    float sl = di * di;
    float4 v = h[n*64 + i];
    float4 acc = make_float4(v.x*sl, v.y*sl, v.z*sl, v.w*sl);
    int k   = g_rowstart[n];
    int end = g_rowstart[n+1];
    for (; k + 8 <= end; k += 8){
        int2 e0 = g_csr[k+0], e1 = g_csr[k+1], e2 = g_csr[k+2], e3 = g_csr[k+3];
        int2 e4 = g_csr[k+4], e5 = g_csr[k+5], e6 = g_csr[k+6], e7 = g_csr[k+7];
        float4 u0 = h[e0.x*64 + i], u1 = h[e1.x*64 + i], u2 = h[e2.x*64 + i], u3 = h[e3.x*64 + i];
        float4 u4 = h[e4.x*64 + i], u5 = h[e5.x*64 + i], u6 = h[e6.x*64 + i], u7 = h[e7.x*64 + i];
        fma4(acc, __int_as_float(e0.y), u0); fma4(acc, __int_as_float(e1.y), u1);
        fma4(acc, __int_as_float(e2.y), u2); fma4(acc, __int_as_float(e3.y), u3);
        fma4(acc, __int_as_float(e4.y), u4); fma4(acc, __int_as_float(e5.y), u5);
        fma4(acc, __int_as_float(e6.y), u6); fma4(acc, __int_as_float(e7.y), u7);
    }
    for (; k + 4 <= end; k += 4){
        int2 e0 = g_csr[k+0], e1 = g_csr[k+1], e2 = g_csr[k+2], e3 = g_csr[k+3];
        float4 u0 = h[e0.x*64 + i], u1 = h[e1.x*64 + i], u2 = h[e2.x*64 + i], u3 = h[e3.x*64 + i];
        fma4(acc, __int_as_float(e0.y), u0); fma4(acc, __int_as_float(e1.y), u1);
        fma4(acc, __int_as_float(e2.y), u2); fma4(acc, __int_as_float(e3.y), u3);
    }
    for (; k < end; k++){
        int2 e = g_csr[k];
        float4 u = h[e.x*64 + i];
        fma4(acc, __int_as_float(e.y), u);
    }
    bf[n*64 + i] = acc;
}

// ---- layer2 input transform: h2 = relu(buf1 + b1) @ W2 ----
__global__ void __launch_bounds__(256) k_xform2(const float* __restrict__ W2, const float* __restrict__ b1){
    __shared__ float sw[256];
    __shared__ float sb[16];
    sw[threadIdx.x] = W2[threadIdx.x];
    if (threadIdx.x < 16) sb[threadIdx.x] = b1[threadIdx.x];
    __syncthreads();
    int r = blockIdx.x*256 + threadIdx.x;
    if (r >= NTOT) return;
    const float4* in = (const float4*)g_buf1 + (size_t)r*4;
    float v[16];
    #pragma unroll
    for (int q=0;q<4;q++){
        float4 t = in[q];
        v[4*q+0]=t.x; v[4*q+1]=t.y; v[4*q+2]=t.z; v[4*q+3]=t.w;
    }
    #pragma unroll
    for (int j=0;j<16;j++) v[j] = fmaxf(v[j] + sb[j], 0.0f);
    float o[16];
    #pragma unroll
    for (int j=0;j<16;j++) o[j] = 0.0f;
    #pragma unroll
    for (int j=0;j<16;j++){
        float vj = v[j];
        #pragma unroll
        for (int jo=0;jo<16;jo++) o[jo] = fmaf(vj, sw[j*16+jo], o[jo]);
    }
    float4* out = (float4*)g_h2 + (size_t)r*4;
    #pragma unroll
    for (int q=0;q<4;q++)
        out[q] = make_float4(o[4*q+0], o[4*q+1], o[4*q+2], o[4*q+3]);
}

// ---- column MLP: col_logits[b*64+c] ----
__global__ void __launch_bounds__(256) k_colmlp(const float* __restrict__ CF, const float* __restrict__ cw1,
                                                const float* __restrict__ cb1, const float* __restrict__ cw2,
                                                const float* __restrict__ cb2){
    __shared__ __align__(16) float sw[FCOL*16];
    __shared__ float sb1[16], sw2[16];
    for (int i = threadIdx.x; i < FCOL*16/4; i += 256)
        ((float4*)sw)[i] = ((const float4*)cw1)[i];
    if (threadIdx.x < 16){ sb1[threadIdx.x]=cb1[threadIdx.x]; sw2[threadIdx.x]=cw2[threadIdx.x]; }
    __syncthreads();
    int r = blockIdx.x*256 + threadIdx.x;
    if (r >= BATCH*NCOL) return;
    const float4* xr = (const float4*)CF + (size_t)r*(FCOL/4);
    float acc[16];
    #pragma unroll
    for (int j=0;j<16;j++) acc[j] = sb1[j];
    for (int k4 = 0; k4 < FCOL/4; k4++){
        float4 xv = xr[k4];
        #pragma unroll
        for (int kk=0; kk<4; kk++){
            float xs = (kk==0)?xv.x:(kk==1)?xv.y:(kk==2)?xv.z:xv.w;
            #pragma unroll
            for (int j=0;j<16;j++) acc[j] = fmaf(xs, sw[(k4*4+kk)*16 + j], acc[j]);
        }
    }
    float sres = cb2[0];
    #pragma unroll
    for (int j=0;j<16;j++) sres = fmaf(fmaxf(acc[j], 0.0f), sw2[j], sres);
    g_col[r] = sres;
}

// ---- final: node head + broadcast add with col logits ----
__global__ void __launch_bounds__(256) k_final(const float* __restrict__ b2, const float* __restrict__ fcw,
                                               const float* __restrict__ fcb, float* __restrict__ out){
    __shared__ __align__(16) float scol[BATCH*NCOL];
    __shared__ float sb2[16], sfw[16];
    for (int i = threadIdx.x; i < BATCH*NCOL; i += 256) scol[i] = g_col[i];
    if (threadIdx.x < 16){ sb2[threadIdx.x]=b2[threadIdx.x]; sfw[threadIdx.x]=fcw[threadIdx.x]; }
    __syncthreads();
    int r = blockIdx.x*256 + threadIdx.x;
    if (r >= NTOT) return;
    int b = r / N_NODES, n = r - b*N_NODES;
    const float4* in = (const float4*)g_buf2 + ((size_t)n*16 + b)*4;
    float logit = fcb[0];
    #pragma unroll
    for (int q=0;q<4;q++){
        float4 t = in[q];
        logit = fmaf(fmaxf(t.x + sb2[4*q+0], 0.0f), sfw[4*q+0], logit);
        logit = fmaf(fmaxf(t.y + sb2[4*q+1], 0.0f), sfw[4*q+1], logit);
        logit = fmaf(fmaxf(t.z + sb2[4*q+2], 0.0f), sfw[4*q+2], logit);
        logit = fmaf(fmaxf(t.w + sb2[4*q+3], 0.0f), sfw[4*q+3], logit);
    }
    float4* o = (float4*)out + (size_t)r*16;          // out[b][n*64 + c]
    const float4* sc = (const float4*)scol + b*16;
    #pragma unroll
    for (int c4 = 0; c4 < 16; c4++){
        float4 cv = sc[c4];
        o[c4] = make_float4(logit+cv.x, logit+cv.y, logit+cv.z, logit+cv.w);
    }
}

extern "C" void kernel_launch(void* const* d_in, const int* in_sizes, int n_in,
                              void* d_out, int out_size){
    const float* X   = (const float*)d_in[0];
    const float* CF  = (const float*)d_in[1];
    const int*   ei  = (const int*)d_in[2];
    const float* W1  = (const float*)d_in[3];
    const float* b1  = (const float*)d_in[4];
    const float* W2  = (const float*)d_in[5];
    const float* b2  = (const float*)d_in[6];
    const float* fcw = (const float*)d_in[7];
    const float* fcb = (const float*)d_in[8];
    const float* cw1 = (const float*)d_in[9];
    const float* cb1 = (const float*)d_in[10];
    const float* cw2 = (const float*)d_in[11];
    const float* cb2 = (const float*)d_in[12];
    float* out = (float*)d_out;

    k_prep  <<<(N_NODES+255)/256, 256>>>(ei);
    k_count <<<(NEDGE+255)/256, 256>>>(ei);
    k_scan  <<<1, 1024>>>();
    k_fill  <<<(NEDGE+255)/256, 256>>>(ei);

    k_gemm1 <<<NTOT/GR, GR>>>(X, W1);
    k_gather<<<(N_NODES*64+255)/256, 256>>>(0);

    k_xform2<<<(NTOT+255)/256, 256>>>(W2, b1);
    k_gather<<<(N_NODES*64+255)/256, 256>>>(1);

    k_colmlp<<<4, 256>>>(CF, cw1, cb1, cw2, cb2);
    k_final <<<(NTOT+255)/256, 256>>>(b2, fcw, fcb, out);
}